// round 1
// baseline (speedup 1.0000x reference)
#include <cuda_runtime.h>
#include <cstdint>

// Problem constants
static constexpr int Lc  = 32;
static constexpr int Kc  = 4;
static constexpr int Dc  = 1024;
static constexpr int QOc = 1024;
static constexpr int KVc = 256;
static constexpr int FFc = 2816;

// Work decomposition: 32 d-rows per block, 256 threads (8 warps x 4 rows/warp).
// Block segments:
//   [0,1024)    : mlp  (W_down, 12 vecs, I=2816)
//   [1024,2048) : q    (W_q, 4 vecs, I=1024, m=0)
//   [2048,3072) : o    (W_o, 4 vecs, I=1024, m=5)
//   [3072,4096) : k    (W_k, 4 vecs, I=256,  m=1)
//   [4096,5120) : v    (W_v, 4 vecs, I=256,  m=2)
//   [5120,5376) : residual copy (grid-stride float4)

template<int M, int I, bool IS_MLP, int MFIX>
__device__ __forceinline__ void proj_tile(
    const float* __restrict__ Wl,   // layer's weight,  [D][I] row-major
    const float* __restrict__ Cl,   // layer's cursed vecs, [M][I]
    float* __restrict__ out,        // full output [L*7*2*K, D]
    int l, int d0)
{
    const int lane  = threadIdx.x & 31;
    const int warp  = threadIdx.x >> 5;
    const int dbase = d0 + warp * 4;

    float acc[4][M];
#pragma unroll
    for (int t = 0; t < 4; ++t)
#pragma unroll
        for (int j = 0; j < M; ++j) acc[t][j] = 0.f;

    const float* wrow = Wl + (size_t)dbase * I;

    // Each chunk: warp covers 128 reduction elements (lane*4 .. lane*4+3).
    for (int c0 = 0; c0 < I; c0 += 128) {
        const int ib = c0 + lane * 4;
        float4 w4[4];
#pragma unroll
        for (int t = 0; t < 4; ++t)
            w4[t] = __ldcg(reinterpret_cast<const float4*>(wrow + (size_t)t * I + ib));
#pragma unroll
        for (int j = 0; j < M; ++j) {
            const float4 c4 = __ldg(reinterpret_cast<const float4*>(Cl + (size_t)j * I + ib));
#pragma unroll
            for (int t = 0; t < 4; ++t) {
                acc[t][j] = fmaf(w4[t].x, c4.x, acc[t][j]);
                acc[t][j] = fmaf(w4[t].y, c4.y, acc[t][j]);
                acc[t][j] = fmaf(w4[t].z, c4.z, acc[t][j]);
                acc[t][j] = fmaf(w4[t].w, c4.w, acc[t][j]);
            }
        }
    }

    // Butterfly reduce each partial across the 32 lanes (all lanes end with sum).
#pragma unroll
    for (int j = 0; j < M; ++j)
#pragma unroll
        for (int t = 0; t < 4; ++t) {
            float v = acc[t][j];
            v += __shfl_xor_sync(0xffffffffu, v, 16);
            v += __shfl_xor_sync(0xffffffffu, v, 8);
            v += __shfl_xor_sync(0xffffffffu, v, 4);
            v += __shfl_xor_sync(0xffffffffu, v, 2);
            v += __shfl_xor_sync(0xffffffffu, v, 1);
            acc[t][j] = v;
        }

    // Scatter stores: result (j,t) written by lane ((j*4+t) & 31).
    // Output row for module m, vec k, s=1 (projected side):
    //   row = ((l*7 + m)*2 + 1)*K + k
#pragma unroll
    for (int j = 0; j < M; ++j) {
        int m, k;
        if (IS_MLP) {
            const int mi = j >> 2;            // 0,1,2 -> gate, up, down
            m = (mi == 2) ? 6 : (3 + mi);     // module order: gate=3, up=4, down=6
            k = j & 3;
        } else {
            m = MFIX;
            k = j;
        }
        const size_t row = ((size_t)(l * 7 + m) * 2 + 1) * Kc + k;
#pragma unroll
        for (int t = 0; t < 4; ++t) {
            if (lane == ((j * 4 + t) & 31))
                out[row * Dc + (size_t)(dbase + t)] = acc[t][j];
        }
    }
}

extern "C" __global__ void __launch_bounds__(256)
both_sides_fused(const float* __restrict__ residual,
                 const float* __restrict__ cq, const float* __restrict__ ck,
                 const float* __restrict__ cv, const float* __restrict__ co,
                 const float* __restrict__ cm,
                 const float* __restrict__ Wq, const float* __restrict__ Wk,
                 const float* __restrict__ Wv, const float* __restrict__ Wo,
                 const float* __restrict__ Wd,
                 float* __restrict__ out)
{
    int b = blockIdx.x;
    if (b < 1024) {                                   // mlp (heaviest first)
        const int l = b >> 5, d0 = (b & 31) * 32;
        proj_tile<12, FFc, true, 0>(Wd + (size_t)l * Dc * FFc,
                                    cm + (size_t)l * 3 * Kc * FFc, out, l, d0);
    } else if (b < 2048) {                            // q (m=0)
        b -= 1024;
        const int l = b >> 5, d0 = (b & 31) * 32;
        proj_tile<4, QOc, false, 0>(Wq + (size_t)l * Dc * QOc,
                                    cq + (size_t)l * Kc * QOc, out, l, d0);
    } else if (b < 3072) {                            // o (m=5)
        b -= 2048;
        const int l = b >> 5, d0 = (b & 31) * 32;
        proj_tile<4, QOc, false, 5>(Wo + (size_t)l * Dc * QOc,
                                    co + (size_t)l * Kc * QOc, out, l, d0);
    } else if (b < 4096) {                            // k (m=1)
        b -= 3072;
        const int l = b >> 5, d0 = (b & 31) * 32;
        proj_tile<4, KVc, false, 1>(Wk + (size_t)l * Dc * KVc,
                                    ck + (size_t)l * Kc * KVc, out, l, d0);
    } else if (b < 5120) {                            // v (m=2)
        b -= 4096;
        const int l = b >> 5, d0 = (b & 31) * 32;
        proj_tile<4, KVc, false, 2>(Wv + (size_t)l * Dc * KVc,
                                    cv + (size_t)l * Kc * KVc, out, l, d0);
    } else {                                          // residual copy, s=0 rows
        const float4* r4 = reinterpret_cast<const float4*>(residual);
        float4* o4 = reinterpret_cast<float4*>(out);
        const int nf4 = Lc * 7 * Kc * Dc / 4;         // 229376 float4
        // residual chunk (l,m): 1024 float4; out stride per chunk: 2048 float4
        for (int i = (b - 5120) * 256 + (int)threadIdx.x; i < nf4; i += 256 * 256) {
            const int chunk  = i >> 10;
            const int within = i & 1023;
            o4[(size_t)chunk * 2048 + within] = r4[i];
        }
    }
}

extern "C" void kernel_launch(void* const* d_in, const int* in_sizes, int n_in,
                              void* d_out, int out_size)
{
    const float* residual = (const float*)d_in[0];
    const float* cq       = (const float*)d_in[1];
    const float* ck       = (const float*)d_in[2];
    const float* cv       = (const float*)d_in[3];
    const float* co       = (const float*)d_in[4];
    const float* cm       = (const float*)d_in[5];
    const float* Wq       = (const float*)d_in[6];
    const float* Wk       = (const float*)d_in[7];
    const float* Wv       = (const float*)d_in[8];
    const float* Wo       = (const float*)d_in[9];
    const float* Wd       = (const float*)d_in[10];
    float* out            = (float*)d_out;

    both_sides_fused<<<5376, 256>>>(residual, cq, ck, cv, co, cm,
                                    Wq, Wk, Wv, Wo, Wd, out);
}

// round 2
// speedup vs baseline: 2.6017x; 2.6017x over previous
#include <cuda_runtime.h>
#include <cstdint>

// Problem constants
static constexpr int Lc  = 32;
static constexpr int Kc  = 4;
static constexpr int Dc  = 1024;
static constexpr int QOc = 1024;
static constexpr int KVc = 256;
static constexpr int FFc = 2816;

static constexpr int S = 256;   // stage width in floats (per cursed vec)

// ---------------- cp.async helpers ----------------
__device__ __forceinline__ void cp_async16(uint32_t saddr, const void* gptr) {
    asm volatile("cp.async.cg.shared.global [%0], [%1], 16;" :: "r"(saddr), "l"(gptr));
}
__device__ __forceinline__ void cp_commit() {
    asm volatile("cp.async.commit_group;");
}
template<int N>
__device__ __forceinline__ void cp_wait() {
    asm volatile("cp.async.wait_group %0;" :: "n"(N));
}

// Stage M x S floats of cursed data (columns [c0, c0+S)) into smem buffer.
template<int M, int I>
__device__ __forceinline__ void stage_cursed(uint32_t sbuf, const float* __restrict__ Cl,
                                             int c0, int tid)
{
    // M * S/4 float4 transfers, 256 threads
#pragma unroll
    for (int idx = tid; idx < M * (S / 4); idx += 256) {
        const int j   = idx >> 6;        // S/4 = 64
        const int col = idx & 63;
        cp_async16(sbuf + (uint32_t)(j * S + col * 4) * 4u,
                   Cl + (size_t)j * I + c0 + col * 4);
    }
}

// ---------------- projection tile ----------------
// Block: 256 threads = 8 warps; each warp owns 4 d-rows; block owns 32 rows.
template<int M, int I, bool IS_MLP, int MFIX>
__device__ __forceinline__ void proj_tile(
    const float* __restrict__ Wl,   // layer weight [D][I]
    const float* __restrict__ Cl,   // layer cursed vecs [M][I]
    float* __restrict__ out,
    float* __restrict__ smem,       // [2][M*S] staging (float, 16B aligned)
    int l, int d0)
{
    const int tid   = threadIdx.x;
    const int lane  = tid & 31;
    const int warp  = tid >> 5;
    const int dbase = d0 + warp * 4;
    const uint32_t smem_u32 = (uint32_t)__cvta_generic_to_shared(smem);
    constexpr int NS = I / S;       // stages

    float acc[4][M];
#pragma unroll
    for (int t = 0; t < 4; ++t)
#pragma unroll
        for (int j = 0; j < M; ++j) acc[t][j] = 0.f;

    const float* wrow = Wl + (size_t)dbase * I;

    // preload stage 0
    stage_cursed<M, I>(smem_u32, Cl, 0, tid);
    cp_commit();

    for (int s = 0; s < NS; ++s) {
        const int c0 = s * S;
        if (s + 1 < NS) {
            stage_cursed<M, I>(smem_u32 + ((s + 1) & 1) * (uint32_t)(M * S * 4),
                               Cl, c0 + S, tid);
            cp_commit();
            cp_wait<1>();
        } else {
            cp_wait<0>();
        }
        __syncthreads();

        const float* cbuf = smem + (s & 1) * (M * S);

        // issue all weight loads for this stage up-front (8 LDG.128 in flight)
        float4 w[2][4];
#pragma unroll
        for (int u = 0; u < 2; ++u)
#pragma unroll
            for (int t = 0; t < 4; ++t)
                w[u][t] = __ldcg(reinterpret_cast<const float4*>(
                    wrow + (size_t)t * I + c0 + u * 128 + lane * 4));

#pragma unroll
        for (int u = 0; u < 2; ++u) {
#pragma unroll
            for (int j = 0; j < M; ++j) {
                const float4 c4 = *reinterpret_cast<const float4*>(
                    cbuf + j * S + u * 128 + lane * 4);
#pragma unroll
                for (int t = 0; t < 4; ++t) {
                    acc[t][j] = fmaf(w[u][t].x, c4.x, acc[t][j]);
                    acc[t][j] = fmaf(w[u][t].y, c4.y, acc[t][j]);
                    acc[t][j] = fmaf(w[u][t].z, c4.z, acc[t][j]);
                    acc[t][j] = fmaf(w[u][t].w, c4.w, acc[t][j]);
                }
            }
        }
        __syncthreads();   // protect buffer before next prefetch overwrites
    }

    // Butterfly reduce across lanes
#pragma unroll
    for (int j = 0; j < M; ++j)
#pragma unroll
        for (int t = 0; t < 4; ++t) {
            float v = acc[t][j];
            v += __shfl_xor_sync(0xffffffffu, v, 16);
            v += __shfl_xor_sync(0xffffffffu, v, 8);
            v += __shfl_xor_sync(0xffffffffu, v, 4);
            v += __shfl_xor_sync(0xffffffffu, v, 2);
            v += __shfl_xor_sync(0xffffffffu, v, 1);
            acc[t][j] = v;
        }

    // Scatter stores (lane ((j*4+t)&31) writes result (j,t))
#pragma unroll
    for (int j = 0; j < M; ++j) {
        int m, k;
        if (IS_MLP) {
            const int mi = j >> 2;            // 0,1,2 -> gate, up, down
            m = (mi == 2) ? 6 : (3 + mi);     // gate=3, up=4, down=6
            k = j & 3;
        } else {
            m = MFIX;
            k = j;
        }
        const size_t row = ((size_t)(l * 7 + m) * 2 + 1) * Kc + k;
#pragma unroll
        for (int t = 0; t < 4; ++t) {
            if (lane == ((j * 4 + t) & 31))
                out[row * Dc + (size_t)(dbase + t)] = acc[t][j];
        }
    }
}

extern "C" __global__ void __launch_bounds__(256, 2)
both_sides_fused(const float* __restrict__ residual,
                 const float* __restrict__ cq, const float* __restrict__ ck,
                 const float* __restrict__ cv, const float* __restrict__ co,
                 const float* __restrict__ cm,
                 const float* __restrict__ Wq, const float* __restrict__ Wk,
                 const float* __restrict__ Wv, const float* __restrict__ Wo,
                 const float* __restrict__ Wd,
                 float* __restrict__ out)
{
    __shared__ __align__(16) float smem[2][12 * S];   // 24 KB

    int b = blockIdx.x;
    if (b < 1024) {                                   // mlp (heaviest first)
        const int l = b >> 5, d0 = (b & 31) * 32;
        proj_tile<12, FFc, true, 0>(Wd + (size_t)l * Dc * FFc,
                                    cm + (size_t)l * 3 * Kc * FFc,
                                    out, &smem[0][0], l, d0);
    } else if (b < 2048) {                            // q (m=0)
        b -= 1024;
        const int l = b >> 5, d0 = (b & 31) * 32;
        proj_tile<4, QOc, false, 0>(Wq + (size_t)l * Dc * QOc,
                                    cq + (size_t)l * Kc * QOc,
                                    out, &smem[0][0], l, d0);
    } else if (b < 3072) {                            // o (m=5)
        b -= 2048;
        const int l = b >> 5, d0 = (b & 31) * 32;
        proj_tile<4, QOc, false, 5>(Wo + (size_t)l * Dc * QOc,
                                    co + (size_t)l * Kc * QOc,
                                    out, &smem[0][0], l, d0);
    } else if (b < 4096) {                            // k (m=1)
        b -= 3072;
        const int l = b >> 5, d0 = (b & 31) * 32;
        proj_tile<4, KVc, false, 1>(Wk + (size_t)l * Dc * KVc,
                                    ck + (size_t)l * Kc * KVc,
                                    out, &smem[0][0], l, d0);
    } else if (b < 5120) {                            // v (m=2)
        b -= 4096;
        const int l = b >> 5, d0 = (b & 31) * 32;
        proj_tile<4, KVc, false, 2>(Wv + (size_t)l * Dc * KVc,
                                    cv + (size_t)l * Kc * KVc,
                                    out, &smem[0][0], l, d0);
    } else {                                          // residual copy (s=0 rows)
        const float4* r4 = reinterpret_cast<const float4*>(residual);
        float4* o4 = reinterpret_cast<float4*>(out);
        const int nf4 = Lc * 7 * Kc * Dc / 4;         // 229376 float4
        for (int i = (b - 5120) * 256 + (int)threadIdx.x; i < nf4; i += 256 * 256) {
            const int chunk  = i >> 10;
            const int within = i & 1023;
            o4[(size_t)chunk * 2048 + within] = r4[i];
        }
    }
}

extern "C" void kernel_launch(void* const* d_in, const int* in_sizes, int n_in,
                              void* d_out, int out_size)
{
    const float* residual = (const float*)d_in[0];
    const float* cq       = (const float*)d_in[1];
    const float* ck       = (const float*)d_in[2];
    const float* cv       = (const float*)d_in[3];
    const float* co       = (const float*)d_in[4];
    const float* cm       = (const float*)d_in[5];
    const float* Wq       = (const float*)d_in[6];
    const float* Wk       = (const float*)d_in[7];
    const float* Wv       = (const float*)d_in[8];
    const float* Wo       = (const float*)d_in[9];
    const float* Wd       = (const float*)d_in[10];
    float* out            = (float*)d_out;

    both_sides_fused<<<5376, 256>>>(residual, cq, ck, cv, co, cm,
                                    Wq, Wk, Wv, Wo, Wd, out);
}